// round 9
// baseline (speedup 1.0000x reference)
#include <cuda_runtime.h>
#include <cuda_fp16.h>
#include <math.h>

#define NMAX   50000
#define EMAX   400000
#define D      64
#define DD     128
#define NBND   64
#define NROWS  65

// Device scratch (zero-init at load; each call leaves din/dout zeroed for the
// next replay; everything else is fully overwritten each call)
__device__ int    g_din[NMAX];
__device__ int    g_dout[NMAX];
__device__ float  g_d0[NMAX];            // in_deg^-1/2
__device__ float  g_d2[NMAX];            // out_deg^-1/2
__device__ int    g_off[NMAX + 1];       // CSR offsets (by dst)
__device__ int    g_cur[NMAX];           // running cursors for permute
__device__ int    g_pe[EMAX * 6];        // permuted edge payload: src, inter[5]
__device__ __align__(16) __half2 g_feath[NMAX * 32];
__device__ __align__(16) __half  g_t2h[NROWS * D];

__device__ __forceinline__ void fmaf2(unsigned long long& c,
                                      unsigned long long a,
                                      unsigned long long b) {
    asm("fma.rn.f32x2 %0, %1, %2, %0;" : "+l"(c) : "l"(a), "l"(b));
}

// acc += tv ⊙ fv (8 halves x 8 halves -> 8 fp32)
__device__ __forceinline__ void acc_prod(uint4 tv, uint4 fv, float4& ca, float4& cb) {
    const __half2* th = (const __half2*)&tv;
    const __half2* fh = (const __half2*)&fv;
    float2 t0 = __half22float2(th[0]), f0 = __half22float2(fh[0]);
    float2 t1 = __half22float2(th[1]), f1 = __half22float2(fh[1]);
    float2 t2 = __half22float2(th[2]), f2 = __half22float2(fh[2]);
    float2 t3 = __half22float2(th[3]), f3 = __half22float2(fh[3]);
    ca.x = fmaf(t0.x, f0.x, ca.x); ca.y = fmaf(t0.y, f0.y, ca.y);
    ca.z = fmaf(t1.x, f1.x, ca.z); ca.w = fmaf(t1.y, f1.y, ca.w);
    cb.x = fmaf(t2.x, f2.x, cb.x); cb.y = fmaf(t2.y, f2.y, cb.y);
    cb.z = fmaf(t3.x, f3.x, cb.z); cb.w = fmaf(t3.y, f3.y, cb.w);
}

// ---------------------------------------------------------------------------
// K1: feat->fp16, degree histogram, fused table fp16
__global__ void setup_kernel(const float* __restrict__ feat,
                             const float* __restrict__ embed,
                             const float* __restrict__ Gw,
                             const int* __restrict__ src,
                             const int* __restrict__ dst,
                             int n, int e) {
    int i = blockIdx.x * blockDim.x + threadIdx.x;
    int stride = gridDim.x * blockDim.x;

    int toth = n * 32;
    for (int k = i; k < toth; k += stride) {
        float2 v = ((const float2*)feat)[k];
        g_feath[k] = __floats2half2_rn(v.x, v.y);
    }
    for (int k = i; k < e; k += stride) {
        atomicAdd(&g_din[dst[k]], 1);
        atomicAdd(&g_dout[src[k]], 1);
    }
    for (int t = i; t < NROWS * D; t += stride) {
        int r = t >> 6;
        int d = t & 63;
        float s = 0.f;
#pragma unroll
        for (int k = 0; k < 32; k++)
            s = fmaf(embed[r * 32 + k], Gw[d * 32 + k], s);
        g_t2h[t] = __float2half_rn(s);
    }
}

// ---------------------------------------------------------------------------
// K2: exclusive scan of g_din -> g_off / g_cur   (single block, 1024 threads)
__global__ void scan_kernel(int n) {
    __shared__ int bs[1024];
    int tid = threadIdx.x;
    int chunk = (n + 1023) >> 10;
    int begin = min(tid * chunk, n);
    int end = min(begin + chunk, n);

    int s = 0;
    for (int i = begin; i < end; i++) s += g_din[i];
    bs[tid] = s;
    __syncthreads();
    for (int off = 1; off < 1024; off <<= 1) {
        int v = (tid >= off) ? bs[tid - off] : 0;
        __syncthreads();
        bs[tid] += v;
        __syncthreads();
    }
    int run = (tid > 0) ? bs[tid - 1] : 0;
    for (int i = begin; i < end; i++) {
        g_off[i] = run;
        g_cur[i] = run;
        run += g_din[i];
    }
    if (end == n && begin < n) g_off[n] = run;
    if (tid == 1023 && n == 0) g_off[0] = 0;
}

// ---------------------------------------------------------------------------
// K3: d0/d2 + re-zero degree counters; permute edge payload into dst order
__global__ void permute_kernel(const int* __restrict__ src,
                               const int* __restrict__ dst,
                               const int* __restrict__ inter,
                               int n, int e) {
    int i = blockIdx.x * blockDim.x + threadIdx.x;
    int stride = gridDim.x * blockDim.x;
    for (int k = i; k < n; k += stride) {
        g_d0[k] = rsqrtf(fmaxf((float)g_din[k], 1.f));
        g_d2[k] = rsqrtf(fmaxf((float)g_dout[k], 1.f));
        g_din[k] = 0;
        g_dout[k] = 0;
    }
    for (int k = i; k < e; k += stride) {
        int dd = dst[k];
        int pos = atomicAdd(&g_cur[dd], 1);
        int b = pos * 6;
        g_pe[b] = src[k];
#pragma unroll
        for (int j = 0; j < 5; j++) g_pe[b + 1 + j] = inter[k * 5 + j];
    }
}

// ---------------------------------------------------------------------------
// K4: fused per-dst aggregation + output GEMM. Persistent blocks, 256 threads.
// 8-lane group per dst node, 32 nodes per tile. Warp-uniform edge loop
// (max over the warp's 4 groups; inactive iterations contribute zero).
#define KP 130
#define SM_WS    0
#define SM_CAT   (D * KP * 4)                 // 33280
#define SM_TS    (SM_CAT + 32 * DD * 4)       // +16384 = 49664
#define SM_SB    (SM_TS + NROWS * 8 * 16)     // +8320  = 57984
#define SM_SS    (SM_SB + NBND * 4)           // +256   = 58240
#define SM_BS    (SM_SS + 32 * 4)             // +128   = 58368
#define SM_TOTAL (SM_BS + D * 4)              // +256   = 58624

__global__ void __launch_bounds__(256) fused_kernel(
        const float2* __restrict__ loc,
        const float* __restrict__ bnd,
        const float* __restrict__ aggw,
        const float* __restrict__ aggb,
        float* __restrict__ out, int n) {
    extern __shared__ char sm[];
    float* Ws   = (float*)(sm + SM_WS);
    float* catS = (float*)(sm + SM_CAT);
    uint4* ts   = (uint4*)(sm + SM_TS);
    float* sb   = (float*)(sm + SM_SB);
    float* ssS  = (float*)(sm + SM_SS);
    float* Bs   = (float*)(sm + SM_BS);

    int tid = threadIdx.x;

    for (int idx = tid; idx < D * DD; idx += 256) {
        int dd = idx >> 7;
        int k  = idx & 127;
        Ws[dd * KP + k] = aggw[idx];
    }
    {
        const uint4* tg = (const uint4*)g_t2h;
        for (int k = tid; k < NROWS * 8; k += 256) ts[k] = tg[k];
    }
    if (tid < NBND) sb[tid] = bnd[tid];
    if (tid < D) Bs[tid] = aggb[tid];
    __syncthreads();
    float guess_scale = 63.0f / fmaxf(sb[NBND - 1], 1e-20f);

    int w    = tid >> 5;
    int lane = tid & 31;
    int grp  = (w << 2) + (lane >> 3);   // 0..31: node group in tile
    int sub  = lane & 7;
    int base = lane & 24;

    const unsigned FULL = 0xffffffffu;
    const uint4* f4 = (const uint4*)g_feath;

    int ntiles = (n + 31) >> 5;
    for (int t = blockIdx.x; t < ntiles; t += gridDim.x) {
        int node = (t << 5) + grp;
        bool nvalid = (node < n);
        int nidx = nvalid ? node : 0;

        int p0 = g_off[nidx];
        int cnt = nvalid ? (g_off[nidx + 1] - p0) : 0;
        float d0v = nvalid ? g_d0[nidx] : 0.f;
        float2 locd = loc[nidx];

        // warp-uniform trip count (all 32 lanes iterate together)
        int maxc = __reduce_max_sync(FULL, cnt);

        float4 a0a = make_float4(0.f, 0.f, 0.f, 0.f);
        float4 a0b = a0a, a1a = a0a, a1b = a0a;
        float ss = 0.f;

        for (int k = 0; k < maxc; k++) {
            bool active = (k < cnt);
            int pos = active ? (p0 + k) : 0;

            int pid = 0;
            if (sub < 6) pid = g_pe[pos * 6 + sub];
            int s_ = __shfl_sync(FULL, pid, base);
            float d2s = active ? g_d2[s_] : 0.f;
            float2 ls = loc[s_];

            int bk = 0;
            if (sub < 6) {
                float2 o = (sub == 0) ? locd : loc[pid];
                float dx = o.x - ls.x;
                float dy = o.y - ls.y;
                float v = sqrtf(dx * dx + dy * dy);
                int kk = (int)ceilf(v * guess_scale);
                kk = min(NBND, max(0, kk));
                while (kk > 0 && sb[kk - 1] >= v) --kk;
                while (kk < NBND && sb[kk] < v) ++kk;
                bk = kk;
            }

            int bks[6], ids[6];
#pragma unroll
            for (int j = 0; j < 6; j++) bks[j] = __shfl_sync(FULL, bk, base + j);
            ids[0] = s_;
#pragma unroll
            for (int j = 1; j < 6; j++) ids[j] = __shfl_sync(FULL, pid, base + j);

            uint4 fv[6];
#pragma unroll
            for (int j = 0; j < 6; j++) fv[j] = f4[ids[j] * 8 + sub];

            float4 e0a = make_float4(0.f, 0.f, 0.f, 0.f);
            float4 e0b = e0a, e1a = e0a, e1b = e0a;
            acc_prod(ts[bks[0] * 8 + sub], fv[0], e0a, e0b);
#pragma unroll
            for (int j = 1; j < 6; j++)
                acc_prod(ts[bks[j] * 8 + sub], fv[j], e1a, e1b);

            // d2s == 0 for inactive iterations -> adds nothing
            a0a.x = fmaf(e0a.x, d2s, a0a.x); a0a.y = fmaf(e0a.y, d2s, a0a.y);
            a0a.z = fmaf(e0a.z, d2s, a0a.z); a0a.w = fmaf(e0a.w, d2s, a0a.w);
            a0b.x = fmaf(e0b.x, d2s, a0b.x); a0b.y = fmaf(e0b.y, d2s, a0b.y);
            a0b.z = fmaf(e0b.z, d2s, a0b.z); a0b.w = fmaf(e0b.w, d2s, a0b.w);
            a1a.x = fmaf(e1a.x, d2s, a1a.x); a1a.y = fmaf(e1a.y, d2s, a1a.y);
            a1a.z = fmaf(e1a.z, d2s, a1a.z); a1a.w = fmaf(e1a.w, d2s, a1a.w);
            a1b.x = fmaf(e1b.x, d2s, a1b.x); a1b.y = fmaf(e1b.y, d2s, a1b.y);
            a1b.z = fmaf(e1b.z, d2s, a1b.z); a1b.w = fmaf(e1b.w, d2s, a1b.w);
            ss += d2s;
        }

        float m = 0.2f * d0v;
        a0a.x *= d0v; a0a.y *= d0v; a0a.z *= d0v; a0a.w *= d0v;
        a0b.x *= d0v; a0b.y *= d0v; a0b.z *= d0v; a0b.w *= d0v;
        a1a.x *= m;   a1a.y *= m;   a1a.z *= m;   a1a.w *= m;
        a1b.x *= m;   a1b.y *= m;   a1b.z *= m;   a1b.w *= m;

        float* cp = catS + grp * DD + sub * 8;
        *(float4*)(cp)          = a0a;
        *(float4*)(cp + 4)      = a0b;
        *(float4*)(cp + D)      = a1a;
        *(float4*)(cp + D + 4)  = a1b;
        if (sub == 0) ssS[grp] = d0v * ss;
        __syncthreads();

        // GEMM phase: warp w -> nodes 4w..4w+3, dims (lane, lane+32)
        unsigned long long acc[4][2];
#pragma unroll
        for (int j = 0; j < 4; j++) { acc[j][0] = 0ull; acc[j][1] = 0ull; }

        const float* wr0 = Ws + lane * KP;
        const float* wr1 = Ws + (lane + 32) * KP;
#pragma unroll 4
        for (int k = 0; k < DD; k += 2) {
            unsigned long long w0 = *(const unsigned long long*)(wr0 + k);
            unsigned long long w1 = *(const unsigned long long*)(wr1 + k);
#pragma unroll
            for (int j = 0; j < 4; j++) {
                unsigned long long aj =
                    *(const unsigned long long*)(catS + ((w << 2) + j) * DD + k);
                fmaf2(acc[j][0], aj, w0);
                fmaf2(acc[j][1], aj, w1);
            }
        }

#pragma unroll
        for (int j = 0; j < 4; j++) {
            int nd = (t << 5) + (w << 2) + j;
            if (nd < n) {
                float sv = ssS[(w << 2) + j];
                float2 q0 = *(float2*)&acc[j][0];
                float2 q1 = *(float2*)&acc[j][1];
                out[nd * D + lane]      = (q0.x + q0.y) + sv * Bs[lane];
                out[nd * D + lane + 32] = (q1.x + q1.y) + sv * Bs[lane + 32];
            }
        }
        __syncthreads();   // catS reused next tile
    }
}

// ---------------------------------------------------------------------------
extern "C" void kernel_launch(void* const* d_in, const int* in_sizes, int n_in,
                              void* d_out, int out_size) {
    const float*  feat  = (const float*)d_in[0];
    const float2* loc   = (const float2*)d_in[1];
    const float*  embed = (const float*)d_in[2];
    const float*  Gw    = (const float*)d_in[3];
    const float*  aggw  = (const float*)d_in[4];
    const float*  aggb  = (const float*)d_in[5];
    const float*  bnd   = (const float*)d_in[6];
    const int*    src   = (const int*)d_in[7];
    const int*    dst   = (const int*)d_in[8];
    const int*    inter = (const int*)d_in[9];
    float* out = (float*)d_out;

    int n = in_sizes[0] / D;   // 50000
    int e = in_sizes[7];       // 400000

    cudaFuncSetAttribute(fused_kernel,
                         cudaFuncAttributeMaxDynamicSharedMemorySize, SM_TOTAL);

    setup_kernel<<<2048, 256>>>(feat, embed, Gw, src, dst, n, e);
    scan_kernel<<<1, 1024>>>(n);
    permute_kernel<<<2048, 256>>>(src, dst, inter, n, e);
    fused_kernel<<<444, 256, SM_TOTAL>>>(loc, bnd, aggw, aggb, out, n);
}

// round 10
// speedup vs baseline: 1.5509x; 1.5509x over previous
#include <cuda_runtime.h>
#include <cuda_fp16.h>
#include <math.h>

#define NMAX   50000
#define EMAX   400000
#define D      64
#define DD     128
#define NBND   64
#define NROWS  65

// Device scratch (zero-init at load; replay-deterministic: setup re-zeroes
// g_acc/g_accs each call, gemm re-zeroes din/dout each call)
__device__ __align__(16) float   g_acc[NMAX * DD];
__device__ float  g_accs[NMAX];
__device__ int    g_din[NMAX];
__device__ int    g_dout[NMAX];
__device__ __align__(16) __half2 g_feath[NMAX * 32];
__device__ __align__(16) __half  g_t2h[NROWS * D];

__device__ __forceinline__ void red_add_v4(float* p, float4 v) {
    asm volatile("red.global.add.v4.f32 [%0], {%1, %2, %3, %4};"
                 :: "l"(p), "f"(v.x), "f"(v.y), "f"(v.z), "f"(v.w)
                 : "memory");
}

__device__ __forceinline__ void fmaf2(unsigned long long& c,
                                      unsigned long long a,
                                      unsigned long long b) {
    asm("fma.rn.f32x2 %0, %1, %2, %0;" : "+l"(c) : "l"(a), "l"(b));
}

__device__ __forceinline__ void acc_prod(uint4 tv, uint4 fv, float4& ca, float4& cb) {
    const __half2* th = (const __half2*)&tv;
    const __half2* fh = (const __half2*)&fv;
    float2 t0 = __half22float2(th[0]), f0 = __half22float2(fh[0]);
    float2 t1 = __half22float2(th[1]), f1 = __half22float2(fh[1]);
    float2 t2 = __half22float2(th[2]), f2 = __half22float2(fh[2]);
    float2 t3 = __half22float2(th[3]), f3 = __half22float2(fh[3]);
    ca.x = fmaf(t0.x, f0.x, ca.x); ca.y = fmaf(t0.y, f0.y, ca.y);
    ca.z = fmaf(t1.x, f1.x, ca.z); ca.w = fmaf(t1.y, f1.y, ca.w);
    cb.x = fmaf(t2.x, f2.x, cb.x); cb.y = fmaf(t2.y, f2.y, cb.y);
    cb.z = fmaf(t3.x, f3.x, cb.z); cb.w = fmaf(t3.y, f3.y, cb.w);
}

// ---------------------------------------------------------------------------
// 0) setup: zero accumulators, convert feat->fp16, degrees, fused table.
__global__ void setup_kernel(const float* __restrict__ feat,
                             const float* __restrict__ embed,
                             const float* __restrict__ Gw,
                             const int* __restrict__ src,
                             const int* __restrict__ dst,
                             int n, int e) {
    int i = blockIdx.x * blockDim.x + threadIdx.x;
    int stride = gridDim.x * blockDim.x;

    int tot4 = n * (DD / 4);
    float4 z = make_float4(0.f, 0.f, 0.f, 0.f);
    for (int k = i; k < tot4; k += stride) ((float4*)g_acc)[k] = z;
    for (int k = i; k < n; k += stride) g_accs[k] = 0.f;

    int toth = n * 32;
    for (int k = i; k < toth; k += stride) {
        float2 v = ((const float2*)feat)[k];
        g_feath[k] = __floats2half2_rn(v.x, v.y);
    }
    for (int k = i; k < e; k += stride) {
        atomicAdd(&g_din[dst[k]], 1);
        atomicAdd(&g_dout[src[k]], 1);
    }
    for (int t = i; t < NROWS * D; t += stride) {
        int r = t >> 6;
        int d = t & 63;
        float s = 0.f;
#pragma unroll
        for (int k = 0; k < 32; k++)
            s = fmaf(embed[r * 32 + k], Gw[d * 32 + k], s);
        g_t2h[t] = __float2half_rn(s);
    }
}

// ---------------------------------------------------------------------------
// 1) edge kernel: 8 lanes/edge. Fused table in SMEM, O(1) bucket search,
//    feat rows prefetched (batched LDG.128). Accumulates d2-weighted cat;
//    d0[dst] is applied later in the gemm (linearity).
__global__ void __launch_bounds__(256, 7) edge_kernel(
        const float2* __restrict__ loc,
        const float* __restrict__ bnd,
        const int* __restrict__ src,
        const int* __restrict__ dst,
        const int* __restrict__ inter,
        int e) {
    __shared__ float sb[NBND];
    __shared__ uint4 ts[NROWS * 8];   // fp16 table rows: 8 uint4 per row

    if (threadIdx.x < NBND) sb[threadIdx.x] = bnd[threadIdx.x];
    {
        const uint4* tg = (const uint4*)g_t2h;
        for (int k = threadIdx.x; k < NROWS * 8; k += 256) ts[k] = tg[k];
    }
    __syncthreads();
    float guess_scale = 63.0f / fmaxf(sb[NBND - 1], 1e-20f);

    int gtid  = blockIdx.x * blockDim.x + threadIdx.x;
    int eidx0 = gtid >> 3;
    int sub   = threadIdx.x & 7;
    int lane  = threadIdx.x & 31;
    int base  = lane & 24;

    bool valid = (eidx0 < e);
    int eidx = valid ? eidx0 : 0;

    int s = src[eidx];
    int d = dst[eidx];
    int dout = g_dout[s];
    float2 ls = loc[s];

    int id = 0;
    if (sub >= 1 && sub <= 5) id = inter[eidx * 5 + (sub - 1)];

    int bk = 0;
    if (sub < 6) {
        float2 o = (sub == 0) ? loc[d] : loc[id];
        float dx = o.x - ls.x;
        float dy = o.y - ls.y;
        float v = sqrtf(dx * dx + dy * dy);
        // searchsorted(side=left): first k with sb[k] >= v. Arithmetic guess,
        // exact fixup (correct for any sorted boundaries).
        int k = (int)ceilf(v * guess_scale);
        k = min(NBND, max(0, k));
        while (k > 0 && sb[k - 1] >= v) --k;
        while (k < NBND && sb[k] < v) ++k;
        bk = k;
    }

    const unsigned FULL = 0xffffffffu;
    const uint4* f4 = (const uint4*)g_feath;

    int bks[6], ids[6];
#pragma unroll
    for (int j = 0; j < 6; j++) bks[j] = __shfl_sync(FULL, bk, base + j);
    ids[0] = s;
#pragma unroll
    for (int j = 1; j < 6; j++) ids[j] = __shfl_sync(FULL, id, base + j);

    // batch the 6 long-latency random feat gathers
    uint4 fv[6];
#pragma unroll
    for (int j = 0; j < 6; j++) fv[j] = f4[ids[j] * 8 + sub];

    float4 c0a = make_float4(0.f, 0.f, 0.f, 0.f);
    float4 c0b = make_float4(0.f, 0.f, 0.f, 0.f);
    acc_prod(ts[bks[0] * 8 + sub], fv[0], c0a, c0b);

    float4 c1a = make_float4(0.f, 0.f, 0.f, 0.f);
    float4 c1b = make_float4(0.f, 0.f, 0.f, 0.f);
#pragma unroll
    for (int j = 1; j < 6; j++)
        acc_prod(ts[bks[j] * 8 + sub], fv[j], c1a, c1b);

    // d2 only; d0[dst] applied in gemm
    float sc = rsqrtf(fmaxf((float)dout, 1.f));
    float m = 0.2f * sc;
    c0a.x *= sc; c0a.y *= sc; c0a.z *= sc; c0a.w *= sc;
    c0b.x *= sc; c0b.y *= sc; c0b.z *= sc; c0b.w *= sc;
    c1a.x *= m;  c1a.y *= m;  c1a.z *= m;  c1a.w *= m;
    c1b.x *= m;  c1b.y *= m;  c1b.z *= m;  c1b.w *= m;

    if (valid) {
        float* p0 = g_acc + d * DD + sub * 8;
        red_add_v4(p0,         c0a);
        red_add_v4(p0 + 4,     c0b);
        red_add_v4(p0 + D,     c1a);
        red_add_v4(p0 + D + 4, c1b);
        if (sub == 0) atomicAdd(&g_accs[d], sc);
    }
}

// ---------------------------------------------------------------------------
// 2) persistent GEMM: out = d0 * (acc @ W^T + accs*b). Reads+zeroes g_din
//    per tile; zeroes g_dout upfront.
#define KP 130
__global__ void gemm_kernel(const float* __restrict__ aggw,
                            const float* __restrict__ aggb,
                            float* __restrict__ out, int n) {
    __shared__ float Ws[D * KP];
    __shared__ float As[16 * KP];
    __shared__ float Ss[16];
    __shared__ float D0s[16];
    __shared__ float Bs[D];

    int tid = threadIdx.x;
    int gi = blockIdx.x * blockDim.x + tid;
    int gstride = gridDim.x * blockDim.x;

    // re-zero out-degree counters (not needed by this kernel)
    for (int k = gi; k < n; k += gstride) g_dout[k] = 0;

    for (int idx = tid; idx < D * DD; idx += 256) {
        int dd = idx >> 7;
        int k  = idx & 127;
        Ws[dd * KP + k] = aggw[idx];
    }
    if (tid < D) Bs[tid] = aggb[tid];

    int ntiles = (n + 15) >> 4;
    int w = tid >> 5;
    int l = tid & 31;

    for (int t = blockIdx.x; t < ntiles; t += gridDim.x) {
        int basev = t << 4;
        __syncthreads();
        for (int idx = tid; idx < 16 * 32; idx += 256) {
            int j = idx >> 5;
            int c = idx & 31;
            int node = basev + j;
            float4 v = make_float4(0.f, 0.f, 0.f, 0.f);
            if (node < n) v = ((const float4*)g_acc)[node * 32 + c];
            float* p = As + j * KP + c * 4;
            *(float2*)p       = make_float2(v.x, v.y);
            *(float2*)(p + 2) = make_float2(v.z, v.w);
        }
        if (tid < 16) {
            int node = basev + tid;
            float ssv = 0.f, d0v = 0.f;
            if (node < n) {
                ssv = g_accs[node];
                int din = g_din[node];
                g_din[node] = 0;   // this block owns this node: safe re-zero
                d0v = rsqrtf(fmaxf((float)din, 1.f));
            }
            Ss[tid]  = ssv;
            D0s[tid] = d0v;
        }
        __syncthreads();

        const float* ar0 = As + (2 * w) * KP;
        const float* ar1 = As + (2 * w + 1) * KP;
        const float* wr0 = Ws + l * KP;
        const float* wr1 = Ws + (l + 32) * KP;

        unsigned long long acc00 = 0ull, acc01 = 0ull, acc10 = 0ull, acc11 = 0ull;
#pragma unroll 8
        for (int k = 0; k < DD; k += 2) {
            unsigned long long a0 = *(const unsigned long long*)(ar0 + k);
            unsigned long long a1 = *(const unsigned long long*)(ar1 + k);
            unsigned long long w0 = *(const unsigned long long*)(wr0 + k);
            unsigned long long w1 = *(const unsigned long long*)(wr1 + k);
            fmaf2(acc00, a0, w0);
            fmaf2(acc01, a0, w1);
            fmaf2(acc10, a1, w0);
            fmaf2(acc11, a1, w1);
        }

        float2 p00 = *(float2*)&acc00;
        float2 p01 = *(float2*)&acc01;
        float2 p10 = *(float2*)&acc10;
        float2 p11 = *(float2*)&acc11;

        int n0 = basev + 2 * w;
        int n1 = n0 + 1;
        if (n0 < n) {
            float d0v = D0s[2 * w];
            float ss  = Ss[2 * w];
            out[n0 * D + l]      = d0v * ((p00.x + p00.y) + ss * Bs[l]);
            out[n0 * D + l + 32] = d0v * ((p01.x + p01.y) + ss * Bs[l + 32]);
        }
        if (n1 < n) {
            float d0v = D0s[2 * w + 1];
            float ss  = Ss[2 * w + 1];
            out[n1 * D + l]      = d0v * ((p10.x + p10.y) + ss * Bs[l]);
            out[n1 * D + l + 32] = d0v * ((p11.x + p11.y) + ss * Bs[l + 32]);
        }
    }
}

// ---------------------------------------------------------------------------
extern "C" void kernel_launch(void* const* d_in, const int* in_sizes, int n_in,
                              void* d_out, int out_size) {
    const float*  feat  = (const float*)d_in[0];
    const float2* loc   = (const float2*)d_in[1];
    const float*  embed = (const float*)d_in[2];
    const float*  Gw    = (const float*)d_in[3];
    const float*  aggw  = (const float*)d_in[4];
    const float*  aggb  = (const float*)d_in[5];
    const float*  bnd   = (const float*)d_in[6];
    const int*    src   = (const int*)d_in[7];
    const int*    dst   = (const int*)d_in[8];
    const int*    inter = (const int*)d_in[9];
    float* out = (float*)d_out;

    int n = in_sizes[0] / D;   // 50000
    int e = in_sizes[7];       // 400000

    setup_kernel<<<4096, 256>>>(feat, embed, Gw, src, dst, n, e);

    long long threads_needed = (long long)e * 8;
    int blocks = (int)((threads_needed + 255) / 256);
    edge_kernel<<<blocks, 256>>>(loc, bnd, src, dst, inter, e);

    gemm_kernel<<<740, 256>>>(aggw, aggb, out, n);
}

// round 11
// speedup vs baseline: 1.7005x; 1.0965x over previous
#include <cuda_runtime.h>
#include <cuda_fp16.h>
#include <math.h>

#define NMAX   50000
#define EMAX   400000
#define D      64
#define DD     128
#define NBND   64
#define NROWS  65

// Device scratch (zero-init at load; replay-deterministic: setup re-zeroes
// g_acc/g_accs each call, gemm re-zeroes din/dout each call)
__device__ __align__(16) float   g_acc[NMAX * DD];
__device__ float  g_accs[NMAX];
__device__ int    g_din[NMAX];
__device__ int    g_dout[NMAX];
__device__ __align__(16) __half2 g_feath[NMAX * 32];
__device__ __align__(16) __half  g_t2h[NROWS * D];

__device__ __forceinline__ void red_add_v4(float* p, float4 v) {
    asm volatile("red.global.add.v4.f32 [%0], {%1, %2, %3, %4};"
                 :: "l"(p), "f"(v.x), "f"(v.y), "f"(v.z), "f"(v.w)
                 : "memory");
}

__device__ __forceinline__ void fmaf2(unsigned long long& c,
                                      unsigned long long a,
                                      unsigned long long b) {
    asm("fma.rn.f32x2 %0, %1, %2, %0;" : "+l"(c) : "l"(a), "l"(b));
}

__device__ __forceinline__ void acc_prod(uint4 tv, uint4 fv, float4& ca, float4& cb) {
    const __half2* th = (const __half2*)&tv;
    const __half2* fh = (const __half2*)&fv;
    float2 t0 = __half22float2(th[0]), f0 = __half22float2(fh[0]);
    float2 t1 = __half22float2(th[1]), f1 = __half22float2(fh[1]);
    float2 t2 = __half22float2(th[2]), f2 = __half22float2(fh[2]);
    float2 t3 = __half22float2(th[3]), f3 = __half22float2(fh[3]);
    ca.x = fmaf(t0.x, f0.x, ca.x); ca.y = fmaf(t0.y, f0.y, ca.y);
    ca.z = fmaf(t1.x, f1.x, ca.z); ca.w = fmaf(t1.y, f1.y, ca.w);
    cb.x = fmaf(t2.x, f2.x, cb.x); cb.y = fmaf(t2.y, f2.y, cb.y);
    cb.z = fmaf(t3.x, f3.x, cb.z); cb.w = fmaf(t3.y, f3.y, cb.w);
}

// ---------------------------------------------------------------------------
// 0) setup: zero accumulators, convert feat->fp16, degrees, fused table.
__global__ void setup_kernel(const float* __restrict__ feat,
                             const float* __restrict__ embed,
                             const float* __restrict__ Gw,
                             const int* __restrict__ src,
                             const int* __restrict__ dst,
                             int n, int e) {
    int i = blockIdx.x * blockDim.x + threadIdx.x;
    int stride = gridDim.x * blockDim.x;

    int tot4 = n * (DD / 4);
    float4 z = make_float4(0.f, 0.f, 0.f, 0.f);
    for (int k = i; k < tot4; k += stride) ((float4*)g_acc)[k] = z;
    for (int k = i; k < n; k += stride) g_accs[k] = 0.f;

    int toth = n * 32;
    for (int k = i; k < toth; k += stride) {
        float2 v = ((const float2*)feat)[k];
        g_feath[k] = __floats2half2_rn(v.x, v.y);
    }
    for (int k = i; k < e; k += stride) {
        atomicAdd(&g_din[dst[k]], 1);
        atomicAdd(&g_dout[src[k]], 1);
    }
    for (int t = i; t < NROWS * D; t += stride) {
        int r = t >> 6;
        int d = t & 63;
        float s = 0.f;
#pragma unroll
        for (int k = 0; k < 32; k++)
            s = fmaf(embed[r * 32 + k], Gw[d * 32 + k], s);
        g_t2h[t] = __float2half_rn(s);
    }
}

// ---------------------------------------------------------------------------
// 1) edge kernel: PERSISTENT blocks, 8 lanes/edge, 32 edges per tile.
//    Table+boundaries staged in smem ONCE per block (amortized over many
//    tiles). O(1) bucket search. d2-only scaling (d0 applied in gemm).
__global__ void edge_kernel(
        const float2* __restrict__ loc,
        const float* __restrict__ bnd,
        const int* __restrict__ src,
        const int* __restrict__ dst,
        const int* __restrict__ inter,
        int e) {
    __shared__ float sb[NBND];
    __shared__ uint4 ts[NROWS * 8];   // fp16 table rows: 8 uint4 per row

    if (threadIdx.x < NBND) sb[threadIdx.x] = bnd[threadIdx.x];
    {
        const uint4* tg = (const uint4*)g_t2h;
        for (int k = threadIdx.x; k < NROWS * 8; k += 256) ts[k] = tg[k];
    }
    __syncthreads();
    float guess_scale = 63.0f / fmaxf(sb[NBND - 1], 1e-20f);

    int grp   = threadIdx.x >> 3;    // 0..31 edge slot within block
    int sub   = threadIdx.x & 7;
    int lane  = threadIdx.x & 31;
    int base  = lane & 24;

    const unsigned FULL = 0xffffffffu;
    const uint4* f4 = (const uint4*)g_feath;

    int ntiles = (e + 31) >> 5;
    for (int t = blockIdx.x; t < ntiles; t += gridDim.x) {
        int eidx0 = (t << 5) + grp;
        bool valid = (eidx0 < e);
        int eidx = valid ? eidx0 : 0;

        int s = src[eidx];
        int d = dst[eidx];
        int dout = g_dout[s];
        float2 ls = loc[s];

        int id = 0;
        if (sub >= 1 && sub <= 5) id = inter[eidx * 5 + (sub - 1)];

        int bk = 0;
        if (sub < 6) {
            float2 o = (sub == 0) ? loc[d] : loc[id];
            float dx = o.x - ls.x;
            float dy = o.y - ls.y;
            float v = sqrtf(dx * dx + dy * dy);
            // searchsorted(side=left): first k with sb[k] >= v.
            int k = (int)ceilf(v * guess_scale);
            k = min(NBND, max(0, k));
            while (k > 0 && sb[k - 1] >= v) --k;
            while (k < NBND && sb[k] < v) ++k;
            bk = k;
        }

        int bks[6], ids[6];
#pragma unroll
        for (int j = 0; j < 6; j++) bks[j] = __shfl_sync(FULL, bk, base + j);
        ids[0] = s;
#pragma unroll
        for (int j = 1; j < 6; j++) ids[j] = __shfl_sync(FULL, id, base + j);

        // batch the 6 long-latency random feat gathers
        uint4 fv[6];
#pragma unroll
        for (int j = 0; j < 6; j++) fv[j] = f4[ids[j] * 8 + sub];

        float4 c0a = make_float4(0.f, 0.f, 0.f, 0.f);
        float4 c0b = make_float4(0.f, 0.f, 0.f, 0.f);
        acc_prod(ts[bks[0] * 8 + sub], fv[0], c0a, c0b);

        float4 c1a = make_float4(0.f, 0.f, 0.f, 0.f);
        float4 c1b = make_float4(0.f, 0.f, 0.f, 0.f);
#pragma unroll
        for (int j = 1; j < 6; j++)
            acc_prod(ts[bks[j] * 8 + sub], fv[j], c1a, c1b);

        // d2 only; d0[dst] applied in gemm (linearity)
        float sc = rsqrtf(fmaxf((float)dout, 1.f));
        float m = 0.2f * sc;
        c0a.x *= sc; c0a.y *= sc; c0a.z *= sc; c0a.w *= sc;
        c0b.x *= sc; c0b.y *= sc; c0b.z *= sc; c0b.w *= sc;
        c1a.x *= m;  c1a.y *= m;  c1a.z *= m;  c1a.w *= m;
        c1b.x *= m;  c1b.y *= m;  c1b.z *= m;  c1b.w *= m;

        if (valid) {
            float* p0 = g_acc + d * DD + sub * 8;
            red_add_v4(p0,         c0a);
            red_add_v4(p0 + 4,     c0b);
            red_add_v4(p0 + D,     c1a);
            red_add_v4(p0 + D + 4, c1b);
            if (sub == 0) atomicAdd(&g_accs[d], sc);
        }
    }
}

// ---------------------------------------------------------------------------
// 2) persistent GEMM: out = d0 * (acc @ W^T + accs*b). 32-node tiles,
//    4 nodes/warp (A reads are smem broadcasts -> halves W-LDS per node).
//    Reads+zeroes g_din per tile; zeroes g_dout upfront.
#define GKP 130
// dynamic smem layout (floats)
#define GS_WS   0                       // 64*130      = 8320 floats
#define GS_AS   (D * GKP)               // +32*128     = 4096
#define GS_SS   (GS_AS + 32 * DD)       // +32
#define GS_D0   (GS_SS + 32)            // +32
#define GS_BS   (GS_D0 + 32)            // +64
#define GS_TOT  ((GS_BS + D) * 4)       // bytes = 50176

__global__ void __launch_bounds__(256) gemm_kernel(
        const float* __restrict__ aggw,
        const float* __restrict__ aggb,
        float* __restrict__ out, int n) {
    extern __shared__ float gsm[];
    float* Ws  = gsm + GS_WS;
    float* As  = gsm + GS_AS;
    float* Ss  = gsm + GS_SS;
    float* D0s = gsm + GS_D0;
    float* Bs  = gsm + GS_BS;

    int tid = threadIdx.x;
    int gi = blockIdx.x * blockDim.x + tid;
    int gstride = gridDim.x * blockDim.x;

    // re-zero out-degree counters (already consumed)
    for (int k = gi; k < n; k += gstride) g_dout[k] = 0;

    for (int idx = tid; idx < D * DD; idx += 256) {
        int dd = idx >> 7;
        int k  = idx & 127;
        Ws[dd * GKP + k] = aggw[idx];
    }
    if (tid < D) Bs[tid] = aggb[tid];

    int ntiles = (n + 31) >> 5;
    int w = tid >> 5;
    int l = tid & 31;

    for (int t = blockIdx.x; t < ntiles; t += gridDim.x) {
        int basev = t << 5;
        __syncthreads();
        // stage 32 acc rows (4 float4 per thread)
        for (int idx = tid; idx < 32 * 32; idx += 256) {
            int j = idx >> 5;
            int c = idx & 31;
            int node = basev + j;
            float4 v = make_float4(0.f, 0.f, 0.f, 0.f);
            if (node < n) v = ((const float4*)g_acc)[node * 32 + c];
            ((float4*)(As + j * DD))[c] = v;
        }
        if (tid < 32) {
            int node = basev + tid;
            float ssv = 0.f, d0v = 0.f;
            if (node < n) {
                ssv = g_accs[node];
                int din = g_din[node];
                g_din[node] = 0;   // this block owns this node
                d0v = rsqrtf(fmaxf((float)din, 1.f));
            }
            Ss[tid]  = ssv;
            D0s[tid] = d0v;
        }
        __syncthreads();

        const float* wr0 = Ws + l * GKP;
        const float* wr1 = Ws + (l + 32) * GKP;
        const float* ar  = As + (w << 2) * DD;

        unsigned long long acc[4][2];
#pragma unroll
        for (int j = 0; j < 4; j++) { acc[j][0] = 0ull; acc[j][1] = 0ull; }

#pragma unroll 4
        for (int k = 0; k < DD; k += 2) {
            unsigned long long w0 = *(const unsigned long long*)(wr0 + k);
            unsigned long long w1 = *(const unsigned long long*)(wr1 + k);
#pragma unroll
            for (int j = 0; j < 4; j++) {
                unsigned long long aj =
                    *(const unsigned long long*)(ar + j * DD + k);
                fmaf2(acc[j][0], aj, w0);
                fmaf2(acc[j][1], aj, w1);
            }
        }

#pragma unroll
        for (int j = 0; j < 4; j++) {
            int nd = basev + (w << 2) + j;
            if (nd < n) {
                float d0v = D0s[(w << 2) + j];
                float ss  = Ss[(w << 2) + j];
                float2 q0 = *(float2*)&acc[j][0];
                float2 q1 = *(float2*)&acc[j][1];
                out[nd * D + l]      = d0v * ((q0.x + q0.y) + ss * Bs[l]);
                out[nd * D + l + 32] = d0v * ((q1.x + q1.y) + ss * Bs[l + 32]);
            }
        }
        __syncthreads();   // As reused next tile
    }
}

// ---------------------------------------------------------------------------
extern "C" void kernel_launch(void* const* d_in, const int* in_sizes, int n_in,
                              void* d_out, int out_size) {
    const float*  feat  = (const float*)d_in[0];
    const float2* loc   = (const float2*)d_in[1];
    const float*  embed = (const float*)d_in[2];
    const float*  Gw    = (const float*)d_in[3];
    const float*  aggw  = (const float*)d_in[4];
    const float*  aggb  = (const float*)d_in[5];
    const float*  bnd   = (const float*)d_in[6];
    const int*    src   = (const int*)d_in[7];
    const int*    dst   = (const int*)d_in[8];
    const int*    inter = (const int*)d_in[9];
    float* out = (float*)d_out;

    int n = in_sizes[0] / D;   // 50000
    int e = in_sizes[7];       // 400000

    cudaFuncSetAttribute(gemm_kernel,
                         cudaFuncAttributeMaxDynamicSharedMemorySize, GS_TOT);

    setup_kernel<<<4096, 256>>>(feat, embed, Gw, src, dst, n, e);
    edge_kernel<<<1184, 256>>>(loc, bnd, src, dst, inter, e);
    gemm_kernel<<<740, 256, GS_TOT>>>(aggw, aggb, out, n);
}

// round 12
// speedup vs baseline: 1.8283x; 1.0752x over previous
#include <cuda_runtime.h>
#include <cuda_fp16.h>
#include <math.h>

#define NMAX   50000
#define EMAX   400000
#define D      64
#define DD     128
#define NBND   64
#define NROWS  65

// Device scratch (zero-init at load; replay-deterministic: setup re-zeroes
// g_acc/g_accs each call, gemm re-zeroes din/dout each call)
__device__ __align__(16) float   g_acc[NMAX * DD];
__device__ float  g_accs[NMAX];
__device__ int    g_din[NMAX];
__device__ int    g_dout[NMAX];
__device__ __align__(16) __half2 g_feath[NMAX * 32];
__device__ __align__(16) __half  g_t2h[NROWS * D];

__device__ __forceinline__ void red_add_v4(float* p, float4 v) {
    asm volatile("red.global.add.v4.f32 [%0], {%1, %2, %3, %4};"
                 :: "l"(p), "f"(v.x), "f"(v.y), "f"(v.z), "f"(v.w)
                 : "memory");
}

__device__ __forceinline__ void fmaf2(unsigned long long& c,
                                      unsigned long long a,
                                      unsigned long long b) {
    asm("fma.rn.f32x2 %0, %1, %2, %0;" : "+l"(c) : "l"(a), "l"(b));
}

__device__ __forceinline__ void acc_prod(uint4 tv, uint4 fv, float4& ca, float4& cb) {
    const __half2* th = (const __half2*)&tv;
    const __half2* fh = (const __half2*)&fv;
    float2 t0 = __half22float2(th[0]), f0 = __half22float2(fh[0]);
    float2 t1 = __half22float2(th[1]), f1 = __half22float2(fh[1]);
    float2 t2 = __half22float2(th[2]), f2 = __half22float2(fh[2]);
    float2 t3 = __half22float2(th[3]), f3 = __half22float2(fh[3]);
    ca.x = fmaf(t0.x, f0.x, ca.x); ca.y = fmaf(t0.y, f0.y, ca.y);
    ca.z = fmaf(t1.x, f1.x, ca.z); ca.w = fmaf(t1.y, f1.y, ca.w);
    cb.x = fmaf(t2.x, f2.x, cb.x); cb.y = fmaf(t2.y, f2.y, cb.y);
    cb.z = fmaf(t3.x, f3.x, cb.z); cb.w = fmaf(t3.y, f3.y, cb.w);
}

// ---------------------------------------------------------------------------
// 0) setup: zero accumulators, convert feat->fp16, degrees, fused table.
__global__ void setup_kernel(const float* __restrict__ feat,
                             const float* __restrict__ embed,
                             const float* __restrict__ Gw,
                             const int* __restrict__ src,
                             const int* __restrict__ dst,
                             int n, int e) {
    int i = blockIdx.x * blockDim.x + threadIdx.x;
    int stride = gridDim.x * blockDim.x;

    int tot4 = n * (DD / 4);
    float4 z = make_float4(0.f, 0.f, 0.f, 0.f);
    for (int k = i; k < tot4; k += stride) ((float4*)g_acc)[k] = z;
    for (int k = i; k < n; k += stride) g_accs[k] = 0.f;

    int toth = n * 32;
    for (int k = i; k < toth; k += stride) {
        float2 v = ((const float2*)feat)[k];
        g_feath[k] = __floats2half2_rn(v.x, v.y);
    }
    for (int k = i; k < e; k += stride) {
        atomicAdd(&g_din[dst[k]], 1);
        atomicAdd(&g_dout[src[k]], 1);
    }
    for (int t = i; t < NROWS * D; t += stride) {
        int r = t >> 6;
        int d = t & 63;
        float s = 0.f;
#pragma unroll
        for (int k = 0; k < 32; k++)
            s = fmaf(embed[r * 32 + k], Gw[d * 32 + k], s);
        g_t2h[t] = __float2half_rn(s);
    }
}

// ---------------------------------------------------------------------------
// 1) edge kernel: PERSISTENT blocks, 8 lanes/edge, 32 edges per tile.
//    Table+boundaries staged in smem ONCE per block. O(1) bucket search.
//    d2-only scaling (d0 applied in gemm via linearity).
__global__ void edge_kernel(
        const float2* __restrict__ loc,
        const float* __restrict__ bnd,
        const int* __restrict__ src,
        const int* __restrict__ dst,
        const int* __restrict__ inter,
        int e) {
    __shared__ float sb[NBND];
    __shared__ uint4 ts[NROWS * 8];   // fp16 table rows: 8 uint4 per row

    if (threadIdx.x < NBND) sb[threadIdx.x] = bnd[threadIdx.x];
    {
        const uint4* tg = (const uint4*)g_t2h;
        for (int k = threadIdx.x; k < NROWS * 8; k += 256) ts[k] = tg[k];
    }
    __syncthreads();
    float guess_scale = 63.0f / fmaxf(sb[NBND - 1], 1e-20f);

    int grp   = threadIdx.x >> 3;    // 0..31 edge slot within block
    int sub   = threadIdx.x & 7;
    int lane  = threadIdx.x & 31;
    int base  = lane & 24;

    const unsigned FULL = 0xffffffffu;
    const uint4* f4 = (const uint4*)g_feath;

    int ntiles = (e + 31) >> 5;
    for (int t = blockIdx.x; t < ntiles; t += gridDim.x) {
        int eidx0 = (t << 5) + grp;
        bool valid = (eidx0 < e);
        int eidx = valid ? eidx0 : 0;

        int s = src[eidx];
        int d = dst[eidx];
        int dout = g_dout[s];
        float2 ls = loc[s];

        int id = 0;
        if (sub >= 1 && sub <= 5) id = inter[eidx * 5 + (sub - 1)];

        int bk = 0;
        if (sub < 6) {
            float2 o = (sub == 0) ? loc[d] : loc[id];
            float dx = o.x - ls.x;
            float dy = o.y - ls.y;
            float v = sqrtf(dx * dx + dy * dy);
            // searchsorted(side=left): first k with sb[k] >= v.
            int k = (int)ceilf(v * guess_scale);
            k = min(NBND, max(0, k));
            while (k > 0 && sb[k - 1] >= v) --k;
            while (k < NBND && sb[k] < v) ++k;
            bk = k;
        }

        int bks[6], ids[6];
#pragma unroll
        for (int j = 0; j < 6; j++) bks[j] = __shfl_sync(FULL, bk, base + j);
        ids[0] = s;
#pragma unroll
        for (int j = 1; j < 6; j++) ids[j] = __shfl_sync(FULL, id, base + j);

        uint4 fv[6];
#pragma unroll
        for (int j = 0; j < 6; j++) fv[j] = f4[ids[j] * 8 + sub];

        float4 c0a = make_float4(0.f, 0.f, 0.f, 0.f);
        float4 c0b = make_float4(0.f, 0.f, 0.f, 0.f);
        acc_prod(ts[bks[0] * 8 + sub], fv[0], c0a, c0b);

        float4 c1a = make_float4(0.f, 0.f, 0.f, 0.f);
        float4 c1b = make_float4(0.f, 0.f, 0.f, 0.f);
#pragma unroll
        for (int j = 1; j < 6; j++)
            acc_prod(ts[bks[j] * 8 + sub], fv[j], c1a, c1b);

        float sc = rsqrtf(fmaxf((float)dout, 1.f));
        float m = 0.2f * sc;
        c0a.x *= sc; c0a.y *= sc; c0a.z *= sc; c0a.w *= sc;
        c0b.x *= sc; c0b.y *= sc; c0b.z *= sc; c0b.w *= sc;
        c1a.x *= m;  c1a.y *= m;  c1a.z *= m;  c1a.w *= m;
        c1b.x *= m;  c1b.y *= m;  c1b.z *= m;  c1b.w *= m;

        if (valid) {
            float* p0 = g_acc + d * DD + sub * 8;
            red_add_v4(p0,         c0a);
            red_add_v4(p0 + 4,     c0b);
            red_add_v4(p0 + D,     c1a);
            red_add_v4(p0 + D + 4, c1b);
            if (sub == 0) atomicAdd(&g_accs[d], sc);
        }
    }
}

// ---------------------------------------------------------------------------
// 2) persistent GEMM v3: out = d0 * (acc @ W^T + accs*b).
//    64-node tiles, 8 nodes/warp, LDS.128 W loads (stride 132: 4-phase
//    conflict-free), LDS.128 broadcast A loads. W staged once per block.
#define WKP 132   // W row stride in floats (132%4==0 for 16B align)
// dynamic smem layout (floats)
#define GS_WS   0                        // 64*132 = 8448
#define GS_AS   (D * WKP)                // +64*128 = 8192
#define GS_SS   (GS_AS + 64 * DD)        // +64
#define GS_D0   (GS_SS + 64)             // +64
#define GS_BS   (GS_D0 + 64)             // +64
#define GS_TOT  ((GS_BS + D) * 4)        // = 67328 bytes

__global__ void __launch_bounds__(256) gemm_kernel(
        const float* __restrict__ aggw,
        const float* __restrict__ aggb,
        float* __restrict__ out, int n) {
    extern __shared__ float gsm[];
    float* Ws  = gsm + GS_WS;
    float* As  = gsm + GS_AS;
    float* Ss  = gsm + GS_SS;
    float* D0s = gsm + GS_D0;
    float* Bs  = gsm + GS_BS;

    int tid = threadIdx.x;
    int gi = blockIdx.x * blockDim.x + tid;
    int gstride = gridDim.x * blockDim.x;

    // re-zero out-degree counters (already consumed by edge_kernel)
    for (int k = gi; k < n; k += gstride) g_dout[k] = 0;

    for (int idx = tid; idx < D * DD; idx += 256) {
        int dd = idx >> 7;
        int k  = idx & 127;
        Ws[dd * WKP + k] = aggw[idx];
    }
    if (tid < D) Bs[tid] = aggb[tid];

    int ntiles = (n + 63) >> 6;
    int w = tid >> 5;
    int l = tid & 31;

    for (int t = blockIdx.x; t < ntiles; t += gridDim.x) {
        int basev = t << 6;
        __syncthreads();
        // stage 64 acc rows (8 float4 per thread)
        for (int idx = tid; idx < 64 * 32; idx += 256) {
            int j = idx >> 5;
            int c = idx & 31;
            int node = basev + j;
            float4 v = make_float4(0.f, 0.f, 0.f, 0.f);
            if (node < n) v = ((const float4*)g_acc)[node * 32 + c];
            ((float4*)(As + j * DD))[c] = v;
        }
        if (tid < 64) {
            int node = basev + tid;
            float ssv = 0.f, d0v = 0.f;
            if (node < n) {
                ssv = g_accs[node];
                int din = g_din[node];
                g_din[node] = 0;   // this block owns this node
                d0v = rsqrtf(fmaxf((float)din, 1.f));
            }
            Ss[tid]  = ssv;
            D0s[tid] = d0v;
        }
        __syncthreads();

        // warp w -> nodes 8w..8w+7; lane l -> dims (l, l+32)
        const float* wr0 = Ws + l * WKP;
        const float* wr1 = Ws + (l + 32) * WKP;
        const float* ar  = As + (w << 3) * DD;

        unsigned long long acc[8][2];
#pragma unroll
        for (int j = 0; j < 8; j++) { acc[j][0] = 0ull; acc[j][1] = 0ull; }

#pragma unroll 2
        for (int k = 0; k < DD; k += 4) {
            float4 w0 = *(const float4*)(wr0 + k);
            float4 w1 = *(const float4*)(wr1 + k);
            unsigned long long w0lo = *(unsigned long long*)&w0.x;
            unsigned long long w0hi = *(unsigned long long*)&w0.z;
            unsigned long long w1lo = *(unsigned long long*)&w1.x;
            unsigned long long w1hi = *(unsigned long long*)&w1.z;
#pragma unroll
            for (int j = 0; j < 8; j++) {
                float4 a = *(const float4*)(ar + j * DD + k);   // broadcast
                unsigned long long alo = *(unsigned long long*)&a.x;
                unsigned long long ahi = *(unsigned long long*)&a.z;
                fmaf2(acc[j][0], alo, w0lo);
                fmaf2(acc[j][0], ahi, w0hi);
                fmaf2(acc[j][1], alo, w1lo);
                fmaf2(acc[j][1], ahi, w1hi);
            }
        }

#pragma unroll
        for (int j = 0; j < 8; j++) {
            int nd = basev + (w << 3) + j;
            if (nd < n) {
                float d0v = D0s[(w << 3) + j];
                float ss  = Ss[(w << 3) + j];
                float2 q0 = *(float2*)&acc[j][0];
                float2 q1 = *(float2*)&acc[j][1];
                out[nd * D + l]      = d0v * ((q0.x + q0.y) + ss * Bs[l]);
                out[nd * D + l + 32] = d0v * ((q1.x + q1.y) + ss * Bs[l + 32]);
            }
        }
        __syncthreads();   // As reused next tile
    }
}

// ---------------------------------------------------------------------------
extern "C" void kernel_launch(void* const* d_in, const int* in_sizes, int n_in,
                              void* d_out, int out_size) {
    const float*  feat  = (const float*)d_in[0];
    const float2* loc   = (const float2*)d_in[1];
    const float*  embed = (const float*)d_in[2];
    const float*  Gw    = (const float*)d_in[3];
    const float*  aggw  = (const float*)d_in[4];
    const float*  aggb  = (const float*)d_in[5];
    const float*  bnd   = (const float*)d_in[6];
    const int*    src   = (const int*)d_in[7];
    const int*    dst   = (const int*)d_in[8];
    const int*    inter = (const int*)d_in[9];
    float* out = (float*)d_out;

    int n = in_sizes[0] / D;   // 50000
    int e = in_sizes[7];       // 400000

    cudaFuncSetAttribute(gemm_kernel,
                         cudaFuncAttributeMaxDynamicSharedMemorySize, GS_TOT);

    setup_kernel<<<4096, 256>>>(feat, embed, Gw, src, dst, n, e);
    edge_kernel<<<1184, 256>>>(loc, bnd, src, dst, inter, e);
    gemm_kernel<<<444, 256, GS_TOT>>>(aggw, aggb, out, n);
}